// round 5
// baseline (speedup 1.0000x reference)
#include <cuda_runtime.h>
#include <cuda_bf16.h>
#include <cstdint>

#define BB 64
#define SS 512
#define HH 768
#define LL 9

__device__ float g_feats[(size_t)BB * SS * LL];
__device__ float g_part[BB];

__device__ __forceinline__ float ex2f_(float x) {
    float y; asm("ex2.approx.ftz.f32 %0, %1;" : "=f"(y) : "f"(x)); return y;
}
__device__ __forceinline__ float lg2f_(float x) {
    float y; asm("lg2.approx.f32 %0, %1;" : "=f"(y) : "f"(x)); return y;
}

// Packed f32x2 FMA (sm_103a): each half is an independent fp32 FMA.
#define FMA_F32X2(d, a, b, c) \
    asm("fma.rn.f32x2 %0, %1, %2, %3;" : "=l"(d) : "l"(a), "l"(b), "l"(c))
#define UNPACK_F32X2_(lo, hi, v) \
    asm("mov.b64 {%0, %1}, %2;" : "=f"(lo), "=f"(hi) : "l"(v))

// ---------------------------------------------------------------------------
// Kernel 1: feats[m][l] = hidden[m][:] . W[l][:] + b[l]   (M=32768,K=768,N=9)
// Chunk-outer, W-in-registers, packed-f32x2 GEMM.
//   warp = 8 rows: lane (q,sl), q=lane>>3 picks row-in-group, sl=lane&7 owns
//   k-slice of 8 per 64-wide chunk; 2 row groups (rows warp*8+q, warp*8+4+q).
//   Per chunk: lane loads W[9][8k] into regs ONCE (18 LDS.128), then 4 LDG.128
//   of hidden + 72 FFMA2. acc is f32x2 (even-k sum, odd-k sum) -> horizontal
//   add at the end, then 3-level shfl reduce over the 8-lane K-split.
// LDS traffic drops 8x vs per-pair-W; FFMA2 halves FMA issue -> DRAM-bound.
// ---------------------------------------------------------------------------
__global__ __launch_bounds__(128)
void gemm_kernel(const float* __restrict__ hidden,
                 const float* __restrict__ W,
                 const float* __restrict__ bias,
                 float* __restrict__ feats) {
    __shared__ ulonglong2 ws[LL * 192];    // W as packed pairs, 27648 B
    const int tid = threadIdx.x;
    const unsigned FULL = 0xffffffffu;

    for (int i = tid; i < LL * 192; i += 128)
        ws[i] = reinterpret_cast<const ulonglong2*>(W)[i];
    __syncthreads();

    const int warp_g = blockIdx.x * 4 + (tid >> 5);   // 0..4095
    const int lane = tid & 31;
    const int q  = lane >> 3;                          // row within group
    const int sl = lane & 7;                           // k-slice

    const int rowA = warp_g * 8 + q;
    const int rowB = rowA + 4;
    const ulonglong2* hpA = reinterpret_cast<const ulonglong2*>(hidden + (size_t)rowA * HH);
    const ulonglong2* hpB = reinterpret_cast<const ulonglong2*>(hidden + (size_t)rowB * HH);

    unsigned long long accA[LL], accB[LL];
#pragma unroll
    for (int l = 0; l < LL; l++) { accA[l] = 0ull; accB[l] = 0ull; }

#pragma unroll 1
    for (int c = 0; c < 12; ++c) {
        const int ib = 16 * c + sl * 2;
        ulonglong2 hA0 = hpA[ib], hA1 = hpA[ib + 1];
        ulonglong2 hB0 = hpB[ib], hB1 = hpB[ib + 1];
#pragma unroll
        for (int l = 0; l < LL; ++l) {
            ulonglong2 wa = ws[l * 192 + ib];
            ulonglong2 wb = ws[l * 192 + ib + 1];
            FMA_F32X2(accA[l], hA0.x, wa.x, accA[l]);
            FMA_F32X2(accB[l], hB0.x, wa.x, accB[l]);
            FMA_F32X2(accA[l], hA0.y, wa.y, accA[l]);
            FMA_F32X2(accB[l], hB0.y, wa.y, accB[l]);
            FMA_F32X2(accA[l], hA1.x, wb.x, accA[l]);
            FMA_F32X2(accB[l], hB1.x, wb.x, accB[l]);
            FMA_F32X2(accA[l], hA1.y, wb.y, accA[l]);
            FMA_F32X2(accB[l], hB1.y, wb.y, accB[l]);
        }
    }

    // horizontal add of the f32x2 halves, then reduce over the 8-lane K-split
    float sA[LL], sB[LL];
#pragma unroll
    for (int l = 0; l < LL; ++l) {
        float lo, hi;
        UNPACK_F32X2_(lo, hi, accA[l]); sA[l] = lo + hi;
        UNPACK_F32X2_(lo, hi, accB[l]); sB[l] = lo + hi;
    }
#pragma unroll
    for (int l = 0; l < LL; ++l) {
        sA[l] += __shfl_xor_sync(FULL, sA[l], 4);
        sB[l] += __shfl_xor_sync(FULL, sB[l], 4);
        sA[l] += __shfl_xor_sync(FULL, sA[l], 2);
        sB[l] += __shfl_xor_sync(FULL, sB[l], 2);
        sA[l] += __shfl_xor_sync(FULL, sA[l], 1);
        sB[l] += __shfl_xor_sync(FULL, sB[l], 1);
    }
    if (sl == 0) {
        float* oA = feats + (size_t)rowA * LL;
        float* oB = feats + (size_t)rowB * LL;
#pragma unroll
        for (int l = 0; l < LL; ++l) {
            float b = __ldg(&bias[l]);
            oA[l] = sA[l] + b;
            oB[l] = sB[l] + b;
        }
    }
}

// ---------------------------------------------------------------------------
// Kernel 2: one block (256 thr, 8 warps) per batch.
// Blocked parallel CRF scan: warp s computes the 9x9 linear-domain transfer
// matrix product over steps t in [max(1,64s), min(len,64(s+1))):
//     M <- M * S_t,  S_t[i][j] = E[i][j] * exp(f_t[j])
// 27 lanes own 3 matrix entries each. Exact power-of-2 rescale every 8 steps.
// Warp 0 then chains alpha0 through the 8 matrices.
// ---------------------------------------------------------------------------
__global__ __launch_bounds__(256, 1)
void crf_kernel(const float* __restrict__ feats,
                const float* __restrict__ start_tr,
                const float* __restrict__ end_tr,
                const float* __restrict__ trans,
                const int* __restrict__ labels,
                const unsigned char* __restrict__ mask8,
                float* __restrict__ partials) {
    __shared__ float sm_ef[SS * LL];       // 18432 B: exp(feats)
    __shared__ float sm_M[8][81];
    __shared__ float sm_C[8];
    __shared__ float sm_red[8];
    __shared__ float sm_score;
    __shared__ int   sm_len;

    const int b = blockIdx.x;
    const int tid = threadIdx.x;
    const int wid = tid >> 5;
    const int lane = tid & 31;
    const unsigned FULL = 0xffffffffu;
    const float LOG2E = 1.4426950408889634f;
    const float LN2   = 0.6931471805599453f;

    // ---- sequence length (mask monotone: mask[t] = t < len) ----
    const unsigned char* mrow = mask8 + (size_t)b * SS;
    int cnt = 0;
    for (int t = tid; t < SS; t += 256) cnt += (int)mrow[t];
    cnt = __reduce_add_sync(FULL, cnt);
    if (lane == 0) sm_red[wid] = (float)cnt;
    __syncthreads();
    if (tid == 0) {
        int l = 0;
        for (int w = 0; w < 8; w++) l += (int)sm_red[w];
        sm_len = l;
    }
    __syncthreads();
    int len = sm_len;
    if (len < SS / 2) {   // fallback: mask stored as int32 (lens >= 256 if u8)
        const int* mi = reinterpret_cast<const int*>(mask8) + (size_t)b * SS;
        cnt = 0;
        for (int t = tid; t < SS; t += 256) cnt += (mi[t] != 0);
        cnt = __reduce_add_sync(FULL, cnt);
        if (lane == 0) sm_red[wid] = (float)cnt;
        __syncthreads();
        if (tid == 0) {
            int l = 0;
            for (int w = 0; w < 8; w++) l += (int)sm_red[w];
            sm_len = l;
        }
        __syncthreads();
        len = sm_len;
    }
    __syncthreads();

    // ---- ef table: sm_ef[t*9+j] = exp(feats[b][t][j]) (vectorized) ----
    const float* frow = feats + (size_t)b * SS * LL;
    for (int i = tid; i < (SS * LL) / 4; i += 256) {
        float4 v = reinterpret_cast<const float4*>(frow)[i];
        float4 e;
        e.x = ex2f_(v.x * LOG2E); e.y = ex2f_(v.y * LOG2E);
        e.z = ex2f_(v.z * LOG2E); e.w = ex2f_(v.w * LOG2E);
        reinterpret_cast<float4*>(sm_ef)[i] = e;
    }

    // ---- gold path score (block-parallel over t) ----
    const int* lab = labels + (size_t)b * SS;
    float sc = 0.f;
    for (int t = tid; t < SS; t += 256) {
        int lt = lab[t];
        if (t == 0) {
            sc += __ldg(&start_tr[lt]) + frow[lt];
        } else if (t < len) {
            sc += __ldg(&trans[lab[t - 1] * LL + lt]) + frow[t * LL + lt];
        }
        if (t == len - 1) sc += __ldg(&end_tr[lt]);
    }
#pragma unroll
    for (int o = 16; o > 0; o >>= 1) sc += __shfl_xor_sync(FULL, sc, o);
    if (lane == 0) sm_red[wid] = sc;
    __syncthreads();
    if (tid == 0) {
        float s = 0.f;
        for (int w = 0; w < 8; w++) s += sm_red[w];
        sm_score = s;
    }

    // ---- per-warp segment matrix product ----
    const int a = (lane < 27) ? (lane / 3) : 8;   // owned row
    const int g = lane % 3;                       // owned col-triple
    float Ec[LL][3];                              // E[i][3g+k]
#pragma unroll
    for (int i = 0; i < LL; i++)
#pragma unroll
        for (int k = 0; k < 3; k++)
            Ec[i][k] = __expf(__ldg(&trans[i * LL + 3 * g + k]));

    float Mr[3];
#pragma unroll
    for (int k = 0; k < 3; k++) Mr[k] = (3 * g + k == a) ? 1.f : 0.f;
    float Cw = 0.f;

    __syncthreads();  // sm_ef ready

    const int t0 = max(1, wid * 64);
    const int t1 = min(len, (wid + 1) * 64);
    for (int t = t0; t < t1; ++t) {
        float ef0 = sm_ef[t * LL + 3 * g + 0];
        float ef1 = sm_ef[t * LL + 3 * g + 1];
        float ef2 = sm_ef[t * LL + 3 * g + 2];

        float m[LL];
#pragma unroll
        for (int i = 0; i < LL; i++)
            m[i] = __shfl_sync(FULL, Mr[i % 3], a * 3 + i / 3);

        float o0a = m[0] * Ec[0][0], o0b = m[1] * Ec[1][0];
        float o1a = m[0] * Ec[0][1], o1b = m[1] * Ec[1][1];
        float o2a = m[0] * Ec[0][2], o2b = m[1] * Ec[1][2];
#pragma unroll
        for (int i = 2; i < LL; i += 2) {
            o0a = fmaf(m[i], Ec[i][0], o0a);
            o1a = fmaf(m[i], Ec[i][1], o1a);
            o2a = fmaf(m[i], Ec[i][2], o2a);
            if (i + 1 < LL) {
                o0b = fmaf(m[i + 1], Ec[i + 1][0], o0b);
                o1b = fmaf(m[i + 1], Ec[i + 1][1], o1b);
                o2b = fmaf(m[i + 1], Ec[i + 1][2], o2b);
            }
        }
        Mr[0] = (o0a + o0b) * ef0;
        Mr[1] = (o1a + o1b) * ef1;
        Mr[2] = (o2a + o2b) * ef2;

        if ((t & 7) == 7) {
            float u = __shfl_sync(FULL, Mr[0], 0);
            int e = (__float_as_int(u) >> 23) & 255;
            float scale = __int_as_float((254 - e) << 23);  // 2^(127-e)
            Mr[0] *= scale; Mr[1] *= scale; Mr[2] *= scale;
            Cw += (float)(e - 127);
        }
    }
    if (lane < 27) {
#pragma unroll
        for (int k = 0; k < 3; k++) sm_M[wid][a * LL + 3 * g + k] = Mr[k];
    }
    if (lane == 0) sm_C[wid] = Cw;
    __syncthreads();

    // ---- warp 0: chain alpha through the 8 segment matrices ----
    if (wid == 0) {
        float al = (lane < LL) ? sm_ef[lane] * __expf(__ldg(&start_tr[lane])) : 0.f;
        float C = 0.f;
#pragma unroll 1
        for (int s = 0; s < 8; ++s) {
            float m[LL];
#pragma unroll
            for (int i = 0; i < LL; i++) m[i] = __shfl_sync(FULL, al, i);
            const int jj = (lane < LL) ? lane : 0;
            float sum = 0.f;
#pragma unroll
            for (int i = 0; i < LL; i++)
                sum = fmaf(m[i], sm_M[s][i * LL + jj], sum);
            al = (lane < LL) ? sum : 0.f;
            C += sm_C[s];
            float u = __shfl_sync(FULL, al, 0);
            int e = (__float_as_int(u) >> 23) & 255;
            float scale = __int_as_float((254 - e) << 23);
            al *= scale;
            C += (float)(e - 127);
        }
        float ev = (lane < LL) ? al * __expf(__ldg(&end_tr[lane])) : 0.f;
#pragma unroll
        for (int o = 16; o > 0; o >>= 1) ev += __shfl_xor_sync(FULL, ev, o);
        float logden = LN2 * (C + lg2f_(ev));
        if (lane == 0) partials[b] = logden - sm_score;
    }
}

// ---------------------------------------------------------------------------
// Kernel 3: mean over 64 per-batch NLLs
// ---------------------------------------------------------------------------
__global__ void finalize_kernel(const float* __restrict__ p, float* __restrict__ out) {
    int lane = threadIdx.x;  // 32 threads
    float v = p[lane] + p[lane + 32];
#pragma unroll
    for (int o = 16; o > 0; o >>= 1) v += __shfl_xor_sync(0xffffffffu, v, o);
    if (lane == 0) out[0] = v * (1.0f / BB);
}

// ---------------------------------------------------------------------------
extern "C" void kernel_launch(void* const* d_in, const int* in_sizes, int n_in,
                              void* d_out, int out_size) {
    const float* hidden  = (const float*)d_in[0];
    const float* W       = (const float*)d_in[1];
    const float* bias    = (const float*)d_in[2];
    const float* start_t = (const float*)d_in[3];
    const float* end_t   = (const float*)d_in[4];
    const float* trans   = (const float*)d_in[5];
    const int*   labels  = (const int*)d_in[6];
    const unsigned char* mask = (const unsigned char*)d_in[7];
    float* out = (float*)d_out;

    float* feats = nullptr;
    float* part  = nullptr;
    cudaGetSymbolAddress((void**)&feats, g_feats);
    cudaGetSymbolAddress((void**)&part,  g_part);

    gemm_kernel<<<1024, 128>>>(hidden, W, bias, feats);
    crf_kernel<<<BB, 256>>>(feats, start_t, end_t, trans, labels, mask, part);
    finalize_kernel<<<1, 32>>>(part, out);
}

// round 6
// speedup vs baseline: 1.4015x; 1.4015x over previous
#include <cuda_runtime.h>
#include <cuda_bf16.h>
#include <cstdint>

#define BB 64
#define SS 512
#define HH 768
#define LL 9

__device__ float g_feats[(size_t)BB * SS * LL];
__device__ float g_part[BB];

__device__ __forceinline__ float ex2f_(float x) {
    float y; asm("ex2.approx.ftz.f32 %0, %1;" : "=f"(y) : "f"(x)); return y;
}
__device__ __forceinline__ float lg2f_(float x) {
    float y; asm("lg2.approx.f32 %0, %1;" : "=f"(y) : "f"(x)); return y;
}

// ---------------------------------------------------------------------------
// Kernel 1: feats[m][l] = hidden[m][:] . W[l][:] + b[l]   (M=32768,K=768,N=9)
// Warp-split-K, 4 rows/warp: lanes 0-15 own rows (r0,r1), lanes 16-31 own
// (r2,r3); lane sl owns K float4 slice {sl+16u}, u=0..11. Each W float4 LDS
// feeds 8 FFMA (2 rows x 4k) -> W smem traffic halved vs 2-row version.
// LDG.128 = 4 lines/instr (fully coalesced). Single-step h prefetch keeps
// regs <= 64 -> 4 blocks/SM, 32 warps, grid 512 = one clean wave, exactly
// 2 quads per warp (zero tail imbalance).
// ---------------------------------------------------------------------------
__global__ __launch_bounds__(256, 4)
void gemm_kernel(const float* __restrict__ hidden,
                 const float* __restrict__ W,
                 const float* __restrict__ bias,
                 float* __restrict__ feats) {
    __shared__ float4 ws4[LL * 192];       // 27648 B
    const int tid = threadIdx.x;
    const unsigned FULL = 0xffffffffu;

    for (int i = tid; i < LL * 192; i += 256)
        ws4[i] = reinterpret_cast<const float4*>(W)[i];
    __syncthreads();

    const int gw   = blockIdx.x * 8 + (tid >> 5);   // 0..4095
    const int lane = tid & 31;
    const int half = lane >> 4;                      // row pair within quad
    const int sl   = lane & 15;                      // k-slice

#pragma unroll 1
    for (int quad = gw; quad < 8192; quad += 4096) {
        const int rowA = quad * 4 + half * 2;
        const int rowB = rowA + 1;
        const float4* hpA = reinterpret_cast<const float4*>(hidden + (size_t)rowA * HH);
        const float4* hpB = reinterpret_cast<const float4*>(hidden + (size_t)rowB * HH);

        float accA[LL], accB[LL];
#pragma unroll
        for (int l = 0; l < LL; l++) { accA[l] = 0.f; accB[l] = 0.f; }

        float4 ha = hpA[sl];
        float4 hb = hpB[sl];

#pragma unroll 2
        for (int u = 0; u < 12; ++u) {
            float4 na, nb;
            if (u < 11) {
                na = hpA[sl + 16 * (u + 1)];
                nb = hpB[sl + 16 * (u + 1)];
            }
            const float4* wrow = ws4 + sl + 16 * u;
#pragma unroll
            for (int l = 0; l < LL; ++l) {
                float4 w = wrow[l * 192];
                accA[l] = fmaf(ha.x, w.x, fmaf(ha.y, w.y,
                          fmaf(ha.z, w.z, fmaf(ha.w, w.w, accA[l]))));
                accB[l] = fmaf(hb.x, w.x, fmaf(hb.y, w.y,
                          fmaf(hb.z, w.z, fmaf(hb.w, w.w, accB[l]))));
            }
            ha = na; hb = nb;
        }

        // reduce the 16-lane K-split (halves are independent; xor<=8 stays
        // within each half)
#pragma unroll
        for (int l = 0; l < LL; ++l) {
            accA[l] += __shfl_xor_sync(FULL, accA[l], 8);
            accB[l] += __shfl_xor_sync(FULL, accB[l], 8);
            accA[l] += __shfl_xor_sync(FULL, accA[l], 4);
            accB[l] += __shfl_xor_sync(FULL, accB[l], 4);
            accA[l] += __shfl_xor_sync(FULL, accA[l], 2);
            accB[l] += __shfl_xor_sync(FULL, accB[l], 2);
            accA[l] += __shfl_xor_sync(FULL, accA[l], 1);
            accB[l] += __shfl_xor_sync(FULL, accB[l], 1);
        }
        if (sl == 0) {
            float* oA = feats + (size_t)rowA * LL;
            float* oB = feats + (size_t)rowB * LL;
#pragma unroll
            for (int l = 0; l < LL; ++l) {
                float b = __ldg(&bias[l]);
                oA[l] = accA[l] + b;
                oB[l] = accB[l] + b;
            }
        }
    }
}

// ---------------------------------------------------------------------------
// Kernel 2: one block (256 thr, 8 warps) per batch.
// Blocked parallel CRF scan: warp s computes the 9x9 linear-domain transfer
// matrix product over steps t in [max(1,64s), min(len,64(s+1))):
//     M <- M * S_t,  S_t[i][j] = E[i][j] * exp(f_t[j])
// 27 lanes own 3 matrix entries each. Exact power-of-2 rescale every 8 steps.
// Warp 0 then chains alpha0 through the 8 matrices.
// ---------------------------------------------------------------------------
__global__ __launch_bounds__(256, 1)
void crf_kernel(const float* __restrict__ feats,
                const float* __restrict__ start_tr,
                const float* __restrict__ end_tr,
                const float* __restrict__ trans,
                const int* __restrict__ labels,
                const unsigned char* __restrict__ mask8,
                float* __restrict__ partials) {
    __shared__ float sm_ef[SS * LL];       // 18432 B: exp(feats)
    __shared__ float sm_M[8][81];
    __shared__ float sm_C[8];
    __shared__ float sm_red[8];
    __shared__ float sm_score;
    __shared__ int   sm_len;

    const int b = blockIdx.x;
    const int tid = threadIdx.x;
    const int wid = tid >> 5;
    const int lane = tid & 31;
    const unsigned FULL = 0xffffffffu;
    const float LOG2E = 1.4426950408889634f;
    const float LN2   = 0.6931471805599453f;

    // ---- sequence length (mask monotone: mask[t] = t < len) ----
    const unsigned char* mrow = mask8 + (size_t)b * SS;
    int cnt = 0;
    for (int t = tid; t < SS; t += 256) cnt += (int)mrow[t];
    cnt = __reduce_add_sync(FULL, cnt);
    if (lane == 0) sm_red[wid] = (float)cnt;
    __syncthreads();
    if (tid == 0) {
        int l = 0;
        for (int w = 0; w < 8; w++) l += (int)sm_red[w];
        sm_len = l;
    }
    __syncthreads();
    int len = sm_len;
    if (len < SS / 2) {   // fallback: mask stored as int32 (lens >= 256 if u8)
        const int* mi = reinterpret_cast<const int*>(mask8) + (size_t)b * SS;
        cnt = 0;
        for (int t = tid; t < SS; t += 256) cnt += (mi[t] != 0);
        cnt = __reduce_add_sync(FULL, cnt);
        if (lane == 0) sm_red[wid] = (float)cnt;
        __syncthreads();
        if (tid == 0) {
            int l = 0;
            for (int w = 0; w < 8; w++) l += (int)sm_red[w];
            sm_len = l;
        }
        __syncthreads();
        len = sm_len;
    }
    __syncthreads();

    // ---- ef table: sm_ef[t*9+j] = exp(feats[b][t][j]) (vectorized) ----
    const float* frow = feats + (size_t)b * SS * LL;
    for (int i = tid; i < (SS * LL) / 4; i += 256) {
        float4 v = reinterpret_cast<const float4*>(frow)[i];
        float4 e;
        e.x = ex2f_(v.x * LOG2E); e.y = ex2f_(v.y * LOG2E);
        e.z = ex2f_(v.z * LOG2E); e.w = ex2f_(v.w * LOG2E);
        reinterpret_cast<float4*>(sm_ef)[i] = e;
    }

    // ---- gold path score (block-parallel over t) ----
    const int* lab = labels + (size_t)b * SS;
    float sc = 0.f;
    for (int t = tid; t < SS; t += 256) {
        int lt = lab[t];
        if (t == 0) {
            sc += __ldg(&start_tr[lt]) + frow[lt];
        } else if (t < len) {
            sc += __ldg(&trans[lab[t - 1] * LL + lt]) + frow[t * LL + lt];
        }
        if (t == len - 1) sc += __ldg(&end_tr[lt]);
    }
#pragma unroll
    for (int o = 16; o > 0; o >>= 1) sc += __shfl_xor_sync(FULL, sc, o);
    if (lane == 0) sm_red[wid] = sc;
    __syncthreads();
    if (tid == 0) {
        float s = 0.f;
        for (int w = 0; w < 8; w++) s += sm_red[w];
        sm_score = s;
    }

    // ---- per-warp segment matrix product ----
    const int a = (lane < 27) ? (lane / 3) : 8;   // owned row
    const int g = lane % 3;                       // owned col-triple
    float Ec[LL][3];                              // E[i][3g+k]
#pragma unroll
    for (int i = 0; i < LL; i++)
#pragma unroll
        for (int k = 0; k < 3; k++)
            Ec[i][k] = __expf(__ldg(&trans[i * LL + 3 * g + k]));

    float Mr[3];
#pragma unroll
    for (int k = 0; k < 3; k++) Mr[k] = (3 * g + k == a) ? 1.f : 0.f;
    float Cw = 0.f;

    __syncthreads();  // sm_ef ready

    const int t0 = max(1, wid * 64);
    const int t1 = min(len, (wid + 1) * 64);
    for (int t = t0; t < t1; ++t) {
        float ef0 = sm_ef[t * LL + 3 * g + 0];
        float ef1 = sm_ef[t * LL + 3 * g + 1];
        float ef2 = sm_ef[t * LL + 3 * g + 2];

        float m[LL];
#pragma unroll
        for (int i = 0; i < LL; i++)
            m[i] = __shfl_sync(FULL, Mr[i % 3], a * 3 + i / 3);

        float o0a = m[0] * Ec[0][0], o0b = m[1] * Ec[1][0];
        float o1a = m[0] * Ec[0][1], o1b = m[1] * Ec[1][1];
        float o2a = m[0] * Ec[0][2], o2b = m[1] * Ec[1][2];
#pragma unroll
        for (int i = 2; i < LL; i += 2) {
            o0a = fmaf(m[i], Ec[i][0], o0a);
            o1a = fmaf(m[i], Ec[i][1], o1a);
            o2a = fmaf(m[i], Ec[i][2], o2a);
            if (i + 1 < LL) {
                o0b = fmaf(m[i + 1], Ec[i + 1][0], o0b);
                o1b = fmaf(m[i + 1], Ec[i + 1][1], o1b);
                o2b = fmaf(m[i + 1], Ec[i + 1][2], o2b);
            }
        }
        Mr[0] = (o0a + o0b) * ef0;
        Mr[1] = (o1a + o1b) * ef1;
        Mr[2] = (o2a + o2b) * ef2;

        if ((t & 7) == 7) {
            float u = __shfl_sync(FULL, Mr[0], 0);
            int e = (__float_as_int(u) >> 23) & 255;
            float scale = __int_as_float((254 - e) << 23);  // 2^(127-e)
            Mr[0] *= scale; Mr[1] *= scale; Mr[2] *= scale;
            Cw += (float)(e - 127);
        }
    }
    if (lane < 27) {
#pragma unroll
        for (int k = 0; k < 3; k++) sm_M[wid][a * LL + 3 * g + k] = Mr[k];
    }
    if (lane == 0) sm_C[wid] = Cw;
    __syncthreads();

    // ---- warp 0: chain alpha through the 8 segment matrices ----
    if (wid == 0) {
        float al = (lane < LL) ? sm_ef[lane] * __expf(__ldg(&start_tr[lane])) : 0.f;
        float C = 0.f;
#pragma unroll 1
        for (int s = 0; s < 8; ++s) {
            float m[LL];
#pragma unroll
            for (int i = 0; i < LL; i++) m[i] = __shfl_sync(FULL, al, i);
            const int jj = (lane < LL) ? lane : 0;
            float sum = 0.f;
#pragma unroll
            for (int i = 0; i < LL; i++)
                sum = fmaf(m[i], sm_M[s][i * LL + jj], sum);
            al = (lane < LL) ? sum : 0.f;
            C += sm_C[s];
            float u = __shfl_sync(FULL, al, 0);
            int e = (__float_as_int(u) >> 23) & 255;
            float scale = __int_as_float((254 - e) << 23);
            al *= scale;
            C += (float)(e - 127);
        }
        float ev = (lane < LL) ? al * __expf(__ldg(&end_tr[lane])) : 0.f;
#pragma unroll
        for (int o = 16; o > 0; o >>= 1) ev += __shfl_xor_sync(FULL, ev, o);
        float logden = LN2 * (C + lg2f_(ev));
        if (lane == 0) partials[b] = logden - sm_score;
    }
}

// ---------------------------------------------------------------------------
// Kernel 3: mean over 64 per-batch NLLs
// ---------------------------------------------------------------------------
__global__ void finalize_kernel(const float* __restrict__ p, float* __restrict__ out) {
    int lane = threadIdx.x;  // 32 threads
    float v = p[lane] + p[lane + 32];
#pragma unroll
    for (int o = 16; o > 0; o >>= 1) v += __shfl_xor_sync(0xffffffffu, v, o);
    if (lane == 0) out[0] = v * (1.0f / BB);
}

// ---------------------------------------------------------------------------
extern "C" void kernel_launch(void* const* d_in, const int* in_sizes, int n_in,
                              void* d_out, int out_size) {
    const float* hidden  = (const float*)d_in[0];
    const float* W       = (const float*)d_in[1];
    const float* bias    = (const float*)d_in[2];
    const float* start_t = (const float*)d_in[3];
    const float* end_t   = (const float*)d_in[4];
    const float* trans   = (const float*)d_in[5];
    const int*   labels  = (const int*)d_in[6];
    const unsigned char* mask = (const unsigned char*)d_in[7];
    float* out = (float*)d_out;

    float* feats = nullptr;
    float* part  = nullptr;
    cudaGetSymbolAddress((void**)&feats, g_feats);
    cudaGetSymbolAddress((void**)&part,  g_part);

    gemm_kernel<<<512, 256>>>(hidden, W, bias, feats);
    crf_kernel<<<BB, 256>>>(feats, start_t, end_t, trans, labels, mask, part);
    finalize_kernel<<<1, 32>>>(part, out);
}